// round 16
// baseline (speedup 1.0000x reference)
#include <cuda_runtime.h>
#include <cuda_fp16.h>
#include <cstdint>
#include <math.h>

#define HH 128
#define WW 128
#define HW (HH*WW)
#define CB 64
#define BB 16

// ---------------- scratch (no cudaMalloc allowed) ----------------
__device__ uint2 g_wmh[BB*2*4*9*4*32];           // main weights [b][z][cc][k][nt4][lane]
__device__ uint2 g_wsh[4*9*2*32];                // SE1 weights  [cc][k][nt2][lane]
__device__ uint2 g_ws2[9*32];                    // SE2 weights  [k][lane] (n=0 col only)
__device__ uint32_t g_hh[(size_t)BB*8*HW];       // SE hidden, half2 ci-pairs [b][cp8][pos]
__device__ float g_mean[BB*CB];                  // pooled means
__device__ uint32_t g_xh[(size_t)BB*32*HW];      // fp16 x, half2 ci-pairs: [b][cp32][pos]

__device__ __forceinline__ uint32_t pack_h2(float lo, float hi) {
    __half2 h = __floats2half2_rn(lo, hi);
    return *reinterpret_cast<uint32_t*>(&h);
}
__device__ __forceinline__ void mma16(float* d, const uint32_t* a, uint32_t b0, uint32_t b1) {
    asm volatile(
        "mma.sync.aligned.m16n8k16.row.col.f32.f16.f16.f32 "
        "{%0,%1,%2,%3}, {%4,%5,%6,%7}, {%8,%9}, {%0,%1,%2,%3};\n"
        : "+f"(d[0]), "+f"(d[1]), "+f"(d[2]), "+f"(d[3])
        : "r"(a[0]), "r"(a[1]), "r"(a[2]), "r"(a[3]), "r"(b0), "r"(b1));
}
__device__ __forceinline__ void cp16z(uint32_t dst, const void* src, bool p) {
    asm volatile("cp.async.cg.shared.global [%0], [%1], 16, %2;"
                 :: "r"(dst), "l"(src), "r"(p ? 16u : 0u));
}
__device__ __forceinline__ void cp16(uint32_t dst, const void* src) {
    asm volatile("cp.async.cg.shared.global [%0], [%1], 16;" :: "r"(dst), "l"(src));
}
#define CP_COMMIT() asm volatile("cp.async.commit_group;" ::: "memory")

__device__ __forceinline__ uint32_t smem_u32(const void* p) {
    uint32_t a;
    asm("{ .reg .u64 t; cvta.to.shared.u64 t, %1; cvt.u32.u64 %0, t; }" : "=r"(a) : "l"(p));
    return a;
}

// ---------------- stage 1: fp16 pack (ci-pairs) + global average pool ----------------
__global__ void __launch_bounds__(256) convert_pool(const float* __restrict__ x, int b0) {
    int cp = blockIdx.x, b = blockIdx.y + b0, t = threadIdx.x;
    const float4* p0 = (const float4*)(x + ((size_t)(b * 64 + 2 * cp)) * HW);
    const float4* p1 = p0 + HW / 4;
    uint4* o = (uint4*)(g_xh + ((size_t)(b * 32 + cp)) * HW);
    float s0 = 0.f, s1 = 0.f;
    #pragma unroll 4
    for (int i = t; i < HW / 4; i += 256) {
        float4 a = p0[i], c = p1[i];
        s0 += (a.x + a.y) + (a.z + a.w);
        s1 += (c.x + c.y) + (c.z + c.w);
        uint4 w;
        w.x = pack_h2(a.x, c.x);
        w.y = pack_h2(a.y, c.y);
        w.z = pack_h2(a.z, c.z);
        w.w = pack_h2(a.w, c.w);
        o[i] = w;
    }
    #pragma unroll
    for (int off = 16; off; off >>= 1) {
        s0 += __shfl_xor_sync(0xffffffffu, s0, off);
        s1 += __shfl_xor_sync(0xffffffffu, s1, off);
    }
    __shared__ float ws0[8], ws1[8];
    if ((t & 31) == 0) { ws0[t >> 5] = s0; ws1[t >> 5] = s1; }
    __syncthreads();
    if (t == 0) {
        float a0 = 0.f, a1 = 0.f;
        #pragma unroll
        for (int i = 0; i < 8; i++) { a0 += ws0[i]; a1 += ws1[i]; }
        g_mean[b * CB + 2 * cp]     = a0 * (1.f / (float)HW);
        g_mean[b * CB + 2 * cp + 1] = a1 * (1.f / (float)HW);
    }
}

// ---------------- stage 2: FC chain + all weight builds (merged) ----------------
#define WM_PER_B (2*4*9*4*32)
#define WS_U2 (4*9*2*32)
__global__ void __launch_bounds__(1024) prep(const float* __restrict__ fc_w1,
                                             const float* __restrict__ fc_w2,
                                             const float* __restrict__ weight,
                                             const float* __restrict__ se_w1,
                                             const float* __restrict__ se_w2, int b0) {
    int b = blockIdx.x + b0, t = threadIdx.x;
    __shared__ float smean[64];
    __shared__ float sh[4];
    __shared__ float sy[576];
    if (t < 64) smean[t] = g_mean[b * 64 + t];
    __syncthreads();
    if (t < 4) {
        float s = 0.f;
        #pragma unroll
        for (int c = 0; c < 64; c++) s += smean[c] * fc_w1[t * 64 + c];
        sh[t] = fmaxf(s, 0.f);
    }
    __syncthreads();
    if (t < 576) {
        float s = 0.f;
        #pragma unroll
        for (int r = 0; r < 4; r++) s += sh[r] * fc_w2[t * 4 + r];
        sy[t] = 1.f / (1.f + expf(-s));
    }
    __syncthreads();
    for (int idx = t; idx < WM_PER_B; idx += 1024) {
        int lane = idx & 31;
        int nt   = (idx >> 5) & 3;
        int k    = (idx >> 7) % 9;
        int rem  = (idx >> 7) / 9;
        int cc   = rem & 3;
        int z    = rem >> 2;
        int g = lane >> 2, tig = lane & 3;
        int co = z * 32 + nt * 8 + g, ci0 = cc * 16;
        float w0 = weight[(co * 64 + ci0 + 2*tig    ) * 9 + k] * sy[(ci0 + 2*tig    ) * 9 + k];
        float w1 = weight[(co * 64 + ci0 + 2*tig + 1) * 9 + k] * sy[(ci0 + 2*tig + 1) * 9 + k];
        float w2 = weight[(co * 64 + ci0 + 2*tig + 8) * 9 + k] * sy[(ci0 + 2*tig + 8) * 9 + k];
        float w3 = weight[(co * 64 + ci0 + 2*tig + 9) * 9 + k] * sy[(ci0 + 2*tig + 9) * 9 + k];
        g_wmh[(size_t)b * WM_PER_B + idx] = make_uint2(pack_h2(w0, w1), pack_h2(w2, w3));
    }
    if (blockIdx.x == 0) {   // first block of EACH quarter writes shared SE tables (same values)
        for (int j = t; j < WS_U2; j += 1024) {
            int lane = j & 31;
            int nt   = (j >> 5) & 1;
            int k    = (j >> 6) % 9;
            int cc   = (j >> 6) / 9;
            int g = lane >> 2, tig = lane & 3;
            int co = nt * 8 + g, ci0 = cc * 16;
            float w0 = se_w1[(co * 64 + ci0 + 2*tig    ) * 9 + k];
            float w1 = se_w1[(co * 64 + ci0 + 2*tig + 1) * 9 + k];
            float w2 = se_w1[(co * 64 + ci0 + 2*tig + 8) * 9 + k];
            float w3 = se_w1[(co * 64 + ci0 + 2*tig + 9) * 9 + k];
            g_wsh[j] = make_uint2(pack_h2(w0, w1), pack_h2(w2, w3));
        }
        if (t < 9 * 32) {
            int k = t >> 5, lane = t & 31;
            int g = lane >> 2, tig = lane & 3;
            float w0 = 0.f, w1 = 0.f, w2 = 0.f, w3 = 0.f;
            if (g == 0) {
                w0 = se_w2[(2*tig    ) * 9 + k];
                w1 = se_w2[(2*tig + 1) * 9 + k];
                w2 = se_w2[(2*tig + 8) * 9 + k];
                w3 = se_w2[(2*tig + 9) * 9 + k];
            }
            g_ws2[t] = make_uint2(pack_h2(w0, w1), pack_h2(w2, w3));
        }
    }
}

#define SX_W 6592               // 8 * 824 words per x/hidden buffer

// ---------------- SE conv1 (NT=2) ----------------
__global__ void __launch_bounds__(512, 2) conv_se(int b0) {
    constexpr int NT = 2;
    constexpr int SW_W = 9 * NT * 64;
    constexpr int BUF_W = SX_W + SW_W;
    extern __shared__ uint32_t sm[];
    const uint32_t smb = smem_u32(sm);
    const int tid = threadIdx.x, wid = tid >> 5, lane = tid & 31;
    const int g = lane >> 2, tig = lane & 3;
    const int b = blockIdx.y + b0, R0 = blockIdx.x * 4;
    const int prow = wid >> 2, colbase = (wid & 3) * 32;

    const int sr = tid >> 3, q = tid & 7;
    const int cp_x = sr / 6, r_x = sr - cp_x * 6;
    const int gy = R0 - 1 + r_x;
    const bool xact = sr < 48;
    const bool rowok = xact && ((unsigned)gy < (unsigned)HH);
    const uint32_t* xrow = g_xh + ((size_t)(b * 32 + cp_x)) * HW + (ptrdiff_t)gy * WW + q * 16;
    const uint32_t dxoff = (uint32_t)(cp_x * 824 + r_x * 136 + 4 + q * 16) * 4;

    if (xact && q == 0) {
        #pragma unroll
        for (int bi = 0; bi < 2; bi++) {
            sm[bi * BUF_W + cp_x * 824 + r_x * 136 + 3]   = 0;
            sm[bi * BUF_W + cp_x * 824 + r_x * 136 + 132] = 0;
        }
    }

    auto stage = [&](int cc, int bufi) {
        const uint32_t bufb = smb + (uint32_t)bufi * (BUF_W * 4);
        if (xact) {
            const uint32_t* src = xrow + (size_t)(cc * 8) * HW;
            const uint32_t dst = bufb + dxoff;
            #pragma unroll
            for (int j = 0; j < 4; j++)
                cp16z(dst + j * 16, src + j * 4, rowok);
        }
        const uint4* wsrc = (const uint4*)(g_wsh + (size_t)cc * (SW_W / 2));
        if (tid < SW_W / 4)
            cp16(bufb + (uint32_t)(SX_W + tid * 4) * 4, wsrc + tid);
    };

    float d[2][NT][4];
    #pragma unroll
    for (int mt = 0; mt < 2; mt++)
        #pragma unroll
        for (int nt = 0; nt < NT; nt++)
            #pragma unroll
            for (int r = 0; r < 4; r++) d[mt][nt][r] = 0.f;

    stage(0, 0);
    CP_COMMIT();

    for (int cc = 0; cc < 4; ++cc) {
        if (cc < 3) {
            stage(cc + 1, (cc + 1) & 1);
            CP_COMMIT();
            asm volatile("cp.async.wait_group 1;" ::: "memory");
        } else {
            asm volatile("cp.async.wait_group 0;" ::: "memory");
        }
        __syncthreads();
        const uint32_t* sxp = sm + (cc & 1) * BUF_W;
        const uint32_t* swp = sxp + SX_W;
        #pragma unroll
        for (int k = 0; k < 9; ++k) {
            const int dy = k / 3, dx = k % 3;
            uint32_t af[2][4];
            #pragma unroll
            for (int mt = 0; mt < 2; ++mt) {
                const int colb = colbase + mt * 16 + g + dx + 3;
                const int b0i = tig * 824 + (prow + dy) * 136 + colb;
                af[mt][0] = sxp[b0i];
                af[mt][1] = sxp[b0i + 8];
                af[mt][2] = sxp[b0i + 4 * 824];
                af[mt][3] = sxp[b0i + 4 * 824 + 8];
            }
            const uint2* swq = (const uint2*)(swp + k * (NT * 64)) + lane;
            #pragma unroll
            for (int nt = 0; nt < NT; ++nt) {
                uint2 w2 = swq[nt * 32];
                mma16(d[0][nt], af[0], w2.x, w2.y);
                mma16(d[1][nt], af[1], w2.x, w2.y);
            }
        }
        __syncthreads();
    }

    const int grow = R0 + prow;
    #pragma unroll
    for (int mt = 0; mt < 2; ++mt) {
        const int col = colbase + mt * 16 + g;
        #pragma unroll
        for (int nt = 0; nt < NT; ++nt) {
            const int cp = nt * 4 + tig;
            uint32_t* hh = g_hh + ((size_t)(b * 8 + cp)) * HW + grow * WW + col;
            hh[0] = pack_h2(fmaxf(d[mt][nt][0], 0.f), fmaxf(d[mt][nt][1], 0.f));
            hh[8] = pack_h2(fmaxf(d[mt][nt][2], 0.f), fmaxf(d[mt][nt][3], 0.f));
        }
    }
}

// ---------------- main conv: all-resident smem, SE2 prologue, z-interleaved taps ------
#define SW4 (9*4*64)      // 2304 words per (z,cc) weight block

__global__ void __launch_bounds__(512, 1) conv_main(float* __restrict__ outp, int b0) {
    extern __shared__ uint32_t sm[];
    const uint32_t smb = smem_u32(sm);
    uint32_t* wall = sm + 5 * SX_W;
    float* sA = (float*)(sm + 5 * SX_W + 8 * SW4);
    const int tid = threadIdx.x, wid = tid >> 5, lane = tid & 31;
    const int g = lane >> 2, tig = lane & 3;
    const int b = blockIdx.y + b0, R0 = blockIdx.x * 4;
    const int prow = wid >> 2, colbase = (wid & 3) * 32;

    const int sr = tid >> 3, q = tid & 7;
    const int cp_x = sr / 6, r_x = sr - cp_x * 6;
    const int gy = R0 - 1 + r_x;
    const bool xact = sr < 48;
    const bool rowok = xact && ((unsigned)gy < (unsigned)HH);
    const uint32_t dxoff_w = (uint32_t)(cp_x * 824 + r_x * 136 + 4 + q * 16);

    if (xact && q == 0) {
        #pragma unroll
        for (int bi = 0; bi < 5; bi++) {
            sm[bi * SX_W + cp_x * 824 + r_x * 136 + 3]   = 0;
            sm[bi * SX_W + cp_x * 824 + r_x * 136 + 132] = 0;
        }
    }

    // ---- issue ALL async copies up front ----
    if (xact) {   // hidden -> buf 0
        const uint32_t* src = g_hh + ((size_t)(b * 8 + cp_x)) * HW + (ptrdiff_t)gy * WW + q * 16;
        const uint32_t dst = smb + dxoff_w * 4;
        #pragma unroll
        for (int j = 0; j < 4; j++) cp16z(dst + j * 16, src + j * 4, rowok);
    }
    CP_COMMIT();                                   // group: hidden
    const uint32_t* xrow = g_xh + ((size_t)(b * 32 + cp_x)) * HW + (ptrdiff_t)gy * WW + q * 16;
    #pragma unroll
    for (int cc = 0; cc < 4; cc++) {               // x chunks -> bufs 1..4
        if (xact) {
            const uint32_t* src = xrow + (size_t)(cc * 8) * HW;
            const uint32_t dst = smb + ((1 + cc) * SX_W + dxoff_w) * 4;
            #pragma unroll
            for (int j = 0; j < 4; j++) cp16z(dst + j * 16, src + j * 4, rowok);
        }
    }
    {   // all 8 weight blocks (contiguous per b): 4608 quads
        const uint4* wsrc = (const uint4*)(g_wmh + (size_t)b * (WM_PER_B / 2) * 2);
        #pragma unroll
        for (int it = 0; it < 9; it++) {
            int idx = tid + it * 512;
            if (idx < 4608)
                cp16(smb + (uint32_t)(5 * SX_W + idx * 4) * 4, wsrc + idx);
        }
    }
    CP_COMMIT();                                   // group: x + weights

    // ---- SE2 on hidden buffer (overlaps x/weight copies) ----
    {
        uint2 wf[9];
        #pragma unroll
        for (int k = 0; k < 9; k++) wf[k] = g_ws2[k * 32 + lane];
        asm volatile("cp.async.wait_group 1;" ::: "memory");   // hidden group done
        __syncthreads();
        float d2[2][4] = {};
        #pragma unroll
        for (int k = 0; k < 9; ++k) {
            const int dy = k / 3, dx = k % 3;
            #pragma unroll
            for (int mt = 0; mt < 2; ++mt) {
                const int colb = colbase + mt * 16 + g + dx + 3;
                const int b0i = tig * 824 + (prow + dy) * 136 + colb;
                uint32_t af[4];
                af[0] = sm[b0i];
                af[1] = sm[b0i + 8];
                af[2] = sm[b0i + 4 * 824];
                af[3] = sm[b0i + 4 * 824 + 8];
                mma16(d2[mt], af, wf[k].x, wf[k].y);
            }
        }
        if (tig == 0) {
            #pragma unroll
            for (int mt = 0; mt < 2; ++mt) {
                const int col = colbase + mt * 16 + g;
                sA[prow * 128 + col]     = 1.f / (1.f + expf(-d2[mt][0]));
                sA[prow * 128 + col + 8] = 1.f / (1.f + expf(-d2[mt][2]));
            }
        }
    }

    asm volatile("cp.async.wait_group 0;" ::: "memory");
    __syncthreads();    // x + weights + sA all visible; no more barriers

    // ---- barrier-free z-interleaved mma loop: af loaded once per tap ----
    float d[2][2][4][4];   // [z][mt][nt][frag] = 64 accums
    #pragma unroll
    for (int z = 0; z < 2; z++)
        #pragma unroll
        for (int mt = 0; mt < 2; mt++)
            #pragma unroll
            for (int nt = 0; nt < 4; nt++)
                #pragma unroll
                for (int r = 0; r < 4; r++) d[z][mt][nt][r] = 0.f;

    for (int cc = 0; cc < 4; ++cc) {
        const uint32_t* sxp = sm + (1 + cc) * SX_W;
        const uint32_t* swp0 = wall + cc * SW4;            // z=0 block
        const uint32_t* swp1 = wall + (4 + cc) * SW4;      // z=1 block
        #pragma unroll
        for (int k = 0; k < 9; ++k) {
            const int dy = k / 3, dx = k % 3;
            uint32_t af[2][4];
            #pragma unroll
            for (int mt = 0; mt < 2; ++mt) {
                const int colb = colbase + mt * 16 + g + dx + 3;
                const int b0i = tig * 824 + (prow + dy) * 136 + colb;
                af[mt][0] = sxp[b0i];
                af[mt][1] = sxp[b0i + 8];
                af[mt][2] = sxp[b0i + 4 * 824];
                af[mt][3] = sxp[b0i + 4 * 824 + 8];
            }
            const uint2* swq0 = (const uint2*)(swp0 + k * 256) + lane;
            const uint2* swq1 = (const uint2*)(swp1 + k * 256) + lane;
            #pragma unroll
            for (int nt = 0; nt < 4; ++nt) {
                uint2 w0 = swq0[nt * 32];
                mma16(d[0][0][nt], af[0], w0.x, w0.y);
                mma16(d[0][1][nt], af[1], w0.x, w0.y);
                uint2 w1 = swq1[nt * 32];
                mma16(d[1][0][nt], af[0], w1.x, w1.y);
                mma16(d[1][1][nt], af[1], w1.x, w1.y);
            }
        }
    }

    // epilogue
    const int grow = R0 + prow;
    #pragma unroll
    for (int z = 0; z < 2; ++z) {
        #pragma unroll
        for (int mt = 0; mt < 2; ++mt) {
            const int col = colbase + mt * 16 + g;
            const float av0 = sA[prow * 128 + col];
            const float av1 = sA[prow * 128 + col + 8];
            #pragma unroll
            for (int nt = 0; nt < 4; ++nt) {
                const int co = z * 32 + nt * 8 + tig * 2;
                float* o0 = outp + ((size_t)(b * 64 + co)) * HW + grow * WW + col;
                float* o1 = o0 + HW;
                o0[0] = d[z][mt][nt][0] * av0;
                o1[0] = d[z][mt][nt][1] * av0;
                o0[8] = d[z][mt][nt][2] * av1;
                o1[8] = d[z][mt][nt][3] * av1;
            }
        }
    }
}

extern "C" void kernel_launch(void* const* d_in, const int* in_sizes, int n_in,
                              void* d_out, int out_size) {
    const float* x      = (const float*)d_in[0];
    const float* weight = (const float*)d_in[1];
    const float* se_w1  = (const float*)d_in[2];
    const float* se_w2  = (const float*)d_in[3];
    const float* fc_w1  = (const float*)d_in[4];
    const float* fc_w2  = (const float*)d_in[5];
    float* out = (float*)d_out;

    const int smem_se   = 2 * (SX_W + 9 * 2 * 64) * 4;                 // 62.0 KB, 2 CTA/SM
    const int smem_main = (5 * SX_W + 8 * SW4 + 512) * 4;              // 202.8 KB, 1 CTA/SM

    constexpr int NS = 4;          // stream-pipelined quarters
    constexpr int QB = BB / NS;    // 4 batches per quarter

    static bool inited = false;
    static cudaStream_t st[NS];    // st[0] = default stream (nullptr)
    static cudaEvent_t eFork[NS], eJoin[NS];
    if (!inited) {
        st[0] = nullptr;
        for (int i = 1; i < NS; i++) cudaStreamCreateWithFlags(&st[i], cudaStreamNonBlocking);
        for (int i = 0; i < NS; i++) {
            cudaEventCreateWithFlags(&eFork[i], cudaEventDisableTiming);
            cudaEventCreateWithFlags(&eJoin[i], cudaEventDisableTiming);
        }
        cudaFuncSetAttribute((const void*)conv_se,
                             cudaFuncAttributeMaxDynamicSharedMemorySize, smem_se);
        cudaFuncSetAttribute((const void*)conv_main,
                             cudaFuncAttributeMaxDynamicSharedMemorySize, smem_main);
        inited = true;
    }

    // fork: bring side streams into the (possibly capturing) default-stream context
    cudaEventRecord(eFork[0], 0);
    for (int i = 1; i < NS; i++) cudaStreamWaitEvent(st[i], eFork[0], 0);

    for (int i = 0; i < NS; i++) {
        const int b0 = i * QB;
        convert_pool<<<dim3(32, QB), 256, 0, st[i]>>>(x, b0);
        prep<<<QB, 1024, 0, st[i]>>>(fc_w1, fc_w2, weight, se_w1, se_w2, b0);
        conv_se<<<dim3(32, QB), 512, smem_se, st[i]>>>(b0);
        conv_main<<<dim3(32, QB), 512, smem_main, st[i]>>>(out, b0);
    }

    // join side streams back into the default stream
    for (int i = 1; i < NS; i++) {
        cudaEventRecord(eJoin[i], st[i]);
        cudaStreamWaitEvent(0, eJoin[i], 0);
    }
}

// round 17
// speedup vs baseline: 1.0067x; 1.0067x over previous
#include <cuda_runtime.h>
#include <cuda_fp16.h>
#include <cstdint>
#include <math.h>

#define HH 128
#define WW 128
#define HW (HH*WW)
#define CB 64
#define BB 16

// ---------------- scratch (no cudaMalloc allowed) ----------------
__device__ uint2 g_wmh[BB*2*4*9*4*32];           // main weights [b][z][cc][k][nt4][lane]
__device__ uint2 g_wsh[4*9*2*32];                // SE1 weights  [cc][k][nt2][lane]
__device__ uint2 g_ws2[9*32];                    // SE2 weights  [k][lane] (n=0 col only)
__device__ uint32_t g_hh[(size_t)BB*8*HW];       // SE hidden, half2 ci-pairs [b][cp8][pos]
__device__ float g_mean[BB*CB];                  // pooled means
__device__ uint32_t g_xh[(size_t)BB*32*HW];      // fp16 x, half2 ci-pairs: [b][cp32][pos]

__device__ __forceinline__ uint32_t pack_h2(float lo, float hi) {
    __half2 h = __floats2half2_rn(lo, hi);
    return *reinterpret_cast<uint32_t*>(&h);
}
__device__ __forceinline__ void mma16(float* d, const uint32_t* a, uint32_t b0, uint32_t b1) {
    asm volatile(
        "mma.sync.aligned.m16n8k16.row.col.f32.f16.f16.f32 "
        "{%0,%1,%2,%3}, {%4,%5,%6,%7}, {%8,%9}, {%0,%1,%2,%3};\n"
        : "+f"(d[0]), "+f"(d[1]), "+f"(d[2]), "+f"(d[3])
        : "r"(a[0]), "r"(a[1]), "r"(a[2]), "r"(a[3]), "r"(b0), "r"(b1));
}
__device__ __forceinline__ void cp16z(uint32_t dst, const void* src, bool p) {
    asm volatile("cp.async.cg.shared.global [%0], [%1], 16, %2;"
                 :: "r"(dst), "l"(src), "r"(p ? 16u : 0u));
}
__device__ __forceinline__ void cp16(uint32_t dst, const void* src) {
    asm volatile("cp.async.cg.shared.global [%0], [%1], 16;" :: "r"(dst), "l"(src));
}
#define CP_COMMIT() asm volatile("cp.async.commit_group;" ::: "memory")

__device__ __forceinline__ uint32_t smem_u32(const void* p) {
    uint32_t a;
    asm("{ .reg .u64 t; cvta.to.shared.u64 t, %1; cvt.u32.u64 %0, t; }" : "=r"(a) : "l"(p));
    return a;
}

// ---------------- stage 1: fp16 pack (ci-pairs) + global average pool ----------------
__global__ void __launch_bounds__(256) convert_pool(const float* __restrict__ x, int b0) {
    int cp = blockIdx.x, b = blockIdx.y + b0, t = threadIdx.x;
    const float4* p0 = (const float4*)(x + ((size_t)(b * 64 + 2 * cp)) * HW);
    const float4* p1 = p0 + HW / 4;
    uint4* o = (uint4*)(g_xh + ((size_t)(b * 32 + cp)) * HW);
    float s0 = 0.f, s1 = 0.f;
    #pragma unroll 4
    for (int i = t; i < HW / 4; i += 256) {
        float4 a = p0[i], c = p1[i];
        s0 += (a.x + a.y) + (a.z + a.w);
        s1 += (c.x + c.y) + (c.z + c.w);
        uint4 w;
        w.x = pack_h2(a.x, c.x);
        w.y = pack_h2(a.y, c.y);
        w.z = pack_h2(a.z, c.z);
        w.w = pack_h2(a.w, c.w);
        o[i] = w;
    }
    #pragma unroll
    for (int off = 16; off; off >>= 1) {
        s0 += __shfl_xor_sync(0xffffffffu, s0, off);
        s1 += __shfl_xor_sync(0xffffffffu, s1, off);
    }
    __shared__ float ws0[8], ws1[8];
    if ((t & 31) == 0) { ws0[t >> 5] = s0; ws1[t >> 5] = s1; }
    __syncthreads();
    if (t == 0) {
        float a0 = 0.f, a1 = 0.f;
        #pragma unroll
        for (int i = 0; i < 8; i++) { a0 += ws0[i]; a1 += ws1[i]; }
        g_mean[b * CB + 2 * cp]     = a0 * (1.f / (float)HW);
        g_mean[b * CB + 2 * cp + 1] = a1 * (1.f / (float)HW);
    }
}

// ---------------- stage 2: FC chain + all weight builds (merged) ----------------
#define WM_PER_B (2*4*9*4*32)
#define WS_U2 (4*9*2*32)
__global__ void __launch_bounds__(1024) prep(const float* __restrict__ fc_w1,
                                             const float* __restrict__ fc_w2,
                                             const float* __restrict__ weight,
                                             const float* __restrict__ se_w1,
                                             const float* __restrict__ se_w2, int b0) {
    int b = blockIdx.x + b0, t = threadIdx.x;
    __shared__ float smean[64];
    __shared__ float sh[4];
    __shared__ float sy[576];
    if (t < 64) smean[t] = g_mean[b * 64 + t];
    __syncthreads();
    if (t < 4) {
        float s = 0.f;
        #pragma unroll
        for (int c = 0; c < 64; c++) s += smean[c] * fc_w1[t * 64 + c];
        sh[t] = fmaxf(s, 0.f);
    }
    __syncthreads();
    if (t < 576) {
        float s = 0.f;
        #pragma unroll
        for (int r = 0; r < 4; r++) s += sh[r] * fc_w2[t * 4 + r];
        sy[t] = 1.f / (1.f + expf(-s));
    }
    __syncthreads();
    for (int idx = t; idx < WM_PER_B; idx += 1024) {
        int lane = idx & 31;
        int nt   = (idx >> 5) & 3;
        int k    = (idx >> 7) % 9;
        int rem  = (idx >> 7) / 9;
        int cc   = rem & 3;
        int z    = rem >> 2;
        int g = lane >> 2, tig = lane & 3;
        int co = z * 32 + nt * 8 + g, ci0 = cc * 16;
        float w0 = weight[(co * 64 + ci0 + 2*tig    ) * 9 + k] * sy[(ci0 + 2*tig    ) * 9 + k];
        float w1 = weight[(co * 64 + ci0 + 2*tig + 1) * 9 + k] * sy[(ci0 + 2*tig + 1) * 9 + k];
        float w2 = weight[(co * 64 + ci0 + 2*tig + 8) * 9 + k] * sy[(ci0 + 2*tig + 8) * 9 + k];
        float w3 = weight[(co * 64 + ci0 + 2*tig + 9) * 9 + k] * sy[(ci0 + 2*tig + 9) * 9 + k];
        g_wmh[(size_t)b * WM_PER_B + idx] = make_uint2(pack_h2(w0, w1), pack_h2(w2, w3));
    }
    if (blockIdx.x == 0) {   // first block of EACH half writes shared SE tables (same values)
        for (int j = t; j < WS_U2; j += 1024) {
            int lane = j & 31;
            int nt   = (j >> 5) & 1;
            int k    = (j >> 6) % 9;
            int cc   = (j >> 6) / 9;
            int g = lane >> 2, tig = lane & 3;
            int co = nt * 8 + g, ci0 = cc * 16;
            float w0 = se_w1[(co * 64 + ci0 + 2*tig    ) * 9 + k];
            float w1 = se_w1[(co * 64 + ci0 + 2*tig + 1) * 9 + k];
            float w2 = se_w1[(co * 64 + ci0 + 2*tig + 8) * 9 + k];
            float w3 = se_w1[(co * 64 + ci0 + 2*tig + 9) * 9 + k];
            g_wsh[j] = make_uint2(pack_h2(w0, w1), pack_h2(w2, w3));
        }
        if (t < 9 * 32) {
            int k = t >> 5, lane = t & 31;
            int g = lane >> 2, tig = lane & 3;
            float w0 = 0.f, w1 = 0.f, w2 = 0.f, w3 = 0.f;
            if (g == 0) {
                w0 = se_w2[(2*tig    ) * 9 + k];
                w1 = se_w2[(2*tig + 1) * 9 + k];
                w2 = se_w2[(2*tig + 8) * 9 + k];
                w3 = se_w2[(2*tig + 9) * 9 + k];
            }
            g_ws2[t] = make_uint2(pack_h2(w0, w1), pack_h2(w2, w3));
        }
    }
}

#define SX_W 6592               // 8 * 824 words per x/hidden buffer

// ---------------- SE conv1 (NT=2) ----------------
__global__ void __launch_bounds__(512, 2) conv_se(int b0) {
    constexpr int NT = 2;
    constexpr int SW_W = 9 * NT * 64;
    constexpr int BUF_W = SX_W + SW_W;
    extern __shared__ uint32_t sm[];
    const uint32_t smb = smem_u32(sm);
    const int tid = threadIdx.x, wid = tid >> 5, lane = tid & 31;
    const int g = lane >> 2, tig = lane & 3;
    const int b = blockIdx.y + b0, R0 = blockIdx.x * 4;
    const int prow = wid >> 2, colbase = (wid & 3) * 32;

    const int sr = tid >> 3, q = tid & 7;
    const int cp_x = sr / 6, r_x = sr - cp_x * 6;
    const int gy = R0 - 1 + r_x;
    const bool xact = sr < 48;
    const bool rowok = xact && ((unsigned)gy < (unsigned)HH);
    const uint32_t* xrow = g_xh + ((size_t)(b * 32 + cp_x)) * HW + (ptrdiff_t)gy * WW + q * 16;
    const uint32_t dxoff = (uint32_t)(cp_x * 824 + r_x * 136 + 4 + q * 16) * 4;

    if (xact && q == 0) {
        #pragma unroll
        for (int bi = 0; bi < 2; bi++) {
            sm[bi * BUF_W + cp_x * 824 + r_x * 136 + 3]   = 0;
            sm[bi * BUF_W + cp_x * 824 + r_x * 136 + 132] = 0;
        }
    }

    auto stage = [&](int cc, int bufi) {
        const uint32_t bufb = smb + (uint32_t)bufi * (BUF_W * 4);
        if (xact) {
            const uint32_t* src = xrow + (size_t)(cc * 8) * HW;
            const uint32_t dst = bufb + dxoff;
            #pragma unroll
            for (int j = 0; j < 4; j++)
                cp16z(dst + j * 16, src + j * 4, rowok);
        }
        const uint4* wsrc = (const uint4*)(g_wsh + (size_t)cc * (SW_W / 2));
        if (tid < SW_W / 4)
            cp16(bufb + (uint32_t)(SX_W + tid * 4) * 4, wsrc + tid);
    };

    float d[2][NT][4];
    #pragma unroll
    for (int mt = 0; mt < 2; mt++)
        #pragma unroll
        for (int nt = 0; nt < NT; nt++)
            #pragma unroll
            for (int r = 0; r < 4; r++) d[mt][nt][r] = 0.f;

    stage(0, 0);
    CP_COMMIT();

    for (int cc = 0; cc < 4; ++cc) {
        if (cc < 3) {
            stage(cc + 1, (cc + 1) & 1);
            CP_COMMIT();
            asm volatile("cp.async.wait_group 1;" ::: "memory");
        } else {
            asm volatile("cp.async.wait_group 0;" ::: "memory");
        }
        __syncthreads();
        const uint32_t* sxp = sm + (cc & 1) * BUF_W;
        const uint32_t* swp = sxp + SX_W;
        #pragma unroll
        for (int k = 0; k < 9; ++k) {
            const int dy = k / 3, dx = k % 3;
            uint32_t af[2][4];
            #pragma unroll
            for (int mt = 0; mt < 2; ++mt) {
                const int colb = colbase + mt * 16 + g + dx + 3;
                const int b0i = tig * 824 + (prow + dy) * 136 + colb;
                af[mt][0] = sxp[b0i];
                af[mt][1] = sxp[b0i + 8];
                af[mt][2] = sxp[b0i + 4 * 824];
                af[mt][3] = sxp[b0i + 4 * 824 + 8];
            }
            const uint2* swq = (const uint2*)(swp + k * (NT * 64)) + lane;
            #pragma unroll
            for (int nt = 0; nt < NT; ++nt) {
                uint2 w2 = swq[nt * 32];
                mma16(d[0][nt], af[0], w2.x, w2.y);
                mma16(d[1][nt], af[1], w2.x, w2.y);
            }
        }
        __syncthreads();
    }

    const int grow = R0 + prow;
    #pragma unroll
    for (int mt = 0; mt < 2; ++mt) {
        const int col = colbase + mt * 16 + g;
        #pragma unroll
        for (int nt = 0; nt < NT; ++nt) {
            const int cp = nt * 4 + tig;
            uint32_t* hh = g_hh + ((size_t)(b * 8 + cp)) * HW + grow * WW + col;
            hh[0] = pack_h2(fmaxf(d[mt][nt][0], 0.f), fmaxf(d[mt][nt][1], 0.f));
            hh[8] = pack_h2(fmaxf(d[mt][nt][2], 0.f), fmaxf(d[mt][nt][3], 0.f));
        }
    }
}

// ---------------- main conv: all-resident smem, SE2 prologue, z-interleaved taps ------
#define SW4 (9*4*64)      // 2304 words per (z,cc) weight block

__global__ void __launch_bounds__(512, 1) conv_main(float* __restrict__ outp, int b0) {
    extern __shared__ uint32_t sm[];
    const uint32_t smb = smem_u32(sm);
    uint32_t* wall = sm + 5 * SX_W;
    float* sA = (float*)(sm + 5 * SX_W + 8 * SW4);
    const int tid = threadIdx.x, wid = tid >> 5, lane = tid & 31;
    const int g = lane >> 2, tig = lane & 3;
    const int b = blockIdx.y + b0, R0 = blockIdx.x * 4;
    const int prow = wid >> 2, colbase = (wid & 3) * 32;

    const int sr = tid >> 3, q = tid & 7;
    const int cp_x = sr / 6, r_x = sr - cp_x * 6;
    const int gy = R0 - 1 + r_x;
    const bool xact = sr < 48;
    const bool rowok = xact && ((unsigned)gy < (unsigned)HH);
    const uint32_t dxoff_w = (uint32_t)(cp_x * 824 + r_x * 136 + 4 + q * 16);

    if (xact && q == 0) {
        #pragma unroll
        for (int bi = 0; bi < 5; bi++) {
            sm[bi * SX_W + cp_x * 824 + r_x * 136 + 3]   = 0;
            sm[bi * SX_W + cp_x * 824 + r_x * 136 + 132] = 0;
        }
    }

    // ---- issue ALL async copies up front ----
    if (xact) {   // hidden -> buf 0
        const uint32_t* src = g_hh + ((size_t)(b * 8 + cp_x)) * HW + (ptrdiff_t)gy * WW + q * 16;
        const uint32_t dst = smb + dxoff_w * 4;
        #pragma unroll
        for (int j = 0; j < 4; j++) cp16z(dst + j * 16, src + j * 4, rowok);
    }
    CP_COMMIT();                                   // group: hidden
    const uint32_t* xrow = g_xh + ((size_t)(b * 32 + cp_x)) * HW + (ptrdiff_t)gy * WW + q * 16;
    #pragma unroll
    for (int cc = 0; cc < 4; cc++) {               // x chunks -> bufs 1..4
        if (xact) {
            const uint32_t* src = xrow + (size_t)(cc * 8) * HW;
            const uint32_t dst = smb + ((1 + cc) * SX_W + dxoff_w) * 4;
            #pragma unroll
            for (int j = 0; j < 4; j++) cp16z(dst + j * 16, src + j * 4, rowok);
        }
    }
    {   // all 8 weight blocks (contiguous per b): 4608 quads
        const uint4* wsrc = (const uint4*)(g_wmh + (size_t)b * (WM_PER_B / 2) * 2);
        #pragma unroll
        for (int it = 0; it < 9; it++) {
            int idx = tid + it * 512;
            if (idx < 4608)
                cp16(smb + (uint32_t)(5 * SX_W + idx * 4) * 4, wsrc + idx);
        }
    }
    CP_COMMIT();                                   // group: x + weights

    // ---- SE2 on hidden buffer (overlaps x/weight copies) ----
    {
        uint2 wf[9];
        #pragma unroll
        for (int k = 0; k < 9; k++) wf[k] = g_ws2[k * 32 + lane];
        asm volatile("cp.async.wait_group 1;" ::: "memory");   // hidden group done
        __syncthreads();
        float d2[2][4] = {};
        #pragma unroll
        for (int k = 0; k < 9; ++k) {
            const int dy = k / 3, dx = k % 3;
            #pragma unroll
            for (int mt = 0; mt < 2; ++mt) {
                const int colb = colbase + mt * 16 + g + dx + 3;
                const int b0i = tig * 824 + (prow + dy) * 136 + colb;
                uint32_t af[4];
                af[0] = sm[b0i];
                af[1] = sm[b0i + 8];
                af[2] = sm[b0i + 4 * 824];
                af[3] = sm[b0i + 4 * 824 + 8];
                mma16(d2[mt], af, wf[k].x, wf[k].y);
            }
        }
        if (tig == 0) {
            #pragma unroll
            for (int mt = 0; mt < 2; ++mt) {
                const int col = colbase + mt * 16 + g;
                sA[prow * 128 + col]     = 1.f / (1.f + expf(-d2[mt][0]));
                sA[prow * 128 + col + 8] = 1.f / (1.f + expf(-d2[mt][2]));
            }
        }
    }

    asm volatile("cp.async.wait_group 0;" ::: "memory");
    __syncthreads();    // x + weights + sA all visible; no more barriers

    // ---- barrier-free z-interleaved mma loop: af loaded once per tap ----
    float d[2][2][4][4];   // [z][mt][nt][frag] = 64 accums
    #pragma unroll
    for (int z = 0; z < 2; z++)
        #pragma unroll
        for (int mt = 0; mt < 2; mt++)
            #pragma unroll
            for (int nt = 0; nt < 4; nt++)
                #pragma unroll
                for (int r = 0; r < 4; r++) d[z][mt][nt][r] = 0.f;

    for (int cc = 0; cc < 4; ++cc) {
        const uint32_t* sxp = sm + (1 + cc) * SX_W;
        const uint32_t* swp0 = wall + cc * SW4;            // z=0 block
        const uint32_t* swp1 = wall + (4 + cc) * SW4;      // z=1 block
        #pragma unroll
        for (int k = 0; k < 9; ++k) {
            const int dy = k / 3, dx = k % 3;
            uint32_t af[2][4];
            #pragma unroll
            for (int mt = 0; mt < 2; ++mt) {
                const int colb = colbase + mt * 16 + g + dx + 3;
                const int b0i = tig * 824 + (prow + dy) * 136 + colb;
                af[mt][0] = sxp[b0i];
                af[mt][1] = sxp[b0i + 8];
                af[mt][2] = sxp[b0i + 4 * 824];
                af[mt][3] = sxp[b0i + 4 * 824 + 8];
            }
            const uint2* swq0 = (const uint2*)(swp0 + k * 256) + lane;
            const uint2* swq1 = (const uint2*)(swp1 + k * 256) + lane;
            #pragma unroll
            for (int nt = 0; nt < 4; ++nt) {
                uint2 w0 = swq0[nt * 32];
                mma16(d[0][0][nt], af[0], w0.x, w0.y);
                mma16(d[0][1][nt], af[1], w0.x, w0.y);
                uint2 w1 = swq1[nt * 32];
                mma16(d[1][0][nt], af[0], w1.x, w1.y);
                mma16(d[1][1][nt], af[1], w1.x, w1.y);
            }
        }
    }

    // epilogue
    const int grow = R0 + prow;
    #pragma unroll
    for (int z = 0; z < 2; ++z) {
        #pragma unroll
        for (int mt = 0; mt < 2; ++mt) {
            const int col = colbase + mt * 16 + g;
            const float av0 = sA[prow * 128 + col];
            const float av1 = sA[prow * 128 + col + 8];
            #pragma unroll
            for (int nt = 0; nt < 4; ++nt) {
                const int co = z * 32 + nt * 8 + tig * 2;
                float* o0 = outp + ((size_t)(b * 64 + co)) * HW + grow * WW + col;
                float* o1 = o0 + HW;
                o0[0] = d[z][mt][nt][0] * av0;
                o1[0] = d[z][mt][nt][1] * av0;
                o0[8] = d[z][mt][nt][2] * av1;
                o1[8] = d[z][mt][nt][3] * av1;
            }
        }
    }
}

extern "C" void kernel_launch(void* const* d_in, const int* in_sizes, int n_in,
                              void* d_out, int out_size) {
    const float* x      = (const float*)d_in[0];
    const float* weight = (const float*)d_in[1];
    const float* se_w1  = (const float*)d_in[2];
    const float* se_w2  = (const float*)d_in[3];
    const float* fc_w1  = (const float*)d_in[4];
    const float* fc_w2  = (const float*)d_in[5];
    float* out = (float*)d_out;

    const int smem_se   = 2 * (SX_W + 9 * 2 * 64) * 4;                 // 62.0 KB, 2 CTA/SM
    const int smem_main = (5 * SX_W + 8 * SW4 + 512) * 4;              // 202.8 KB, 1 CTA/SM

    static bool inited = false;
    static cudaStream_t s1, s2;    // BOTH halves on non-default streams (no legacy serialization)
    static cudaEvent_t eFork, eJ1, eJ2;
    if (!inited) {
        cudaStreamCreateWithFlags(&s1, cudaStreamNonBlocking);
        cudaStreamCreateWithFlags(&s2, cudaStreamNonBlocking);
        cudaEventCreateWithFlags(&eFork, cudaEventDisableTiming);
        cudaEventCreateWithFlags(&eJ1, cudaEventDisableTiming);
        cudaEventCreateWithFlags(&eJ2, cudaEventDisableTiming);
        cudaFuncSetAttribute((const void*)conv_se,
                             cudaFuncAttributeMaxDynamicSharedMemorySize, smem_se);
        cudaFuncSetAttribute((const void*)conv_main,
                             cudaFuncAttributeMaxDynamicSharedMemorySize, smem_main);
        inited = true;
    }

    // fork from the (possibly capturing) default stream into s1 and s2
    cudaEventRecord(eFork, 0);
    cudaStreamWaitEvent(s1, eFork, 0);
    cudaStreamWaitEvent(s2, eFork, 0);

    // half H0 (batches 0..7) on s1
    convert_pool<<<dim3(32, BB/2), 256, 0, s1>>>(x, 0);
    prep<<<BB/2, 1024, 0, s1>>>(fc_w1, fc_w2, weight, se_w1, se_w2, 0);
    conv_se<<<dim3(32, BB/2), 512, smem_se, s1>>>(0);
    conv_main<<<dim3(32, BB/2), 512, smem_main, s1>>>(out, 0);

    // half H1 (batches 8..15) on s2
    convert_pool<<<dim3(32, BB/2), 256, 0, s2>>>(x, BB/2);
    prep<<<BB/2, 1024, 0, s2>>>(fc_w1, fc_w2, weight, se_w1, se_w2, BB/2);
    conv_se<<<dim3(32, BB/2), 512, smem_se, s2>>>(BB/2);
    conv_main<<<dim3(32, BB/2), 512, smem_main, s2>>>(out, BB/2);

    // join both streams back into the default stream
    cudaEventRecord(eJ1, s1);
    cudaEventRecord(eJ2, s2);
    cudaStreamWaitEvent(0, eJ1, 0);
    cudaStreamWaitEvent(0, eJ2, 0);
}